// round 1
// baseline (speedup 1.0000x reference)
#include <cuda_runtime.h>

#define NN 100000
#define NE 1600000
#define NT_EDGE 1700000   // edges + self loops
#define NG 256

// ---------------- scratch (static device allocations; no runtime alloc) ----
__device__ int   g_cnt[NN];
__device__ int   g_fill[NN];
__device__ float g_dinv[NN];
__device__ int   g_rowptr[NN + 1];
__device__ int2  g_edata[NT_EDGE];          // {src, float_as_int(norm)} bucketed by dst
__device__ float g_agg[NN * 108];           // aggregation output (max width 108)
__device__ float g_h1[NN * 64];             // layer1 out, 54 real cols, stride 64
__device__ float g_h2[NN * 128];            // layer2 out, 108 real cols, stride 128
__device__ float g_h3[NN * 224];            // layer3 out, 216 real cols, stride 224
__device__ float g_Wp1[54 * 64],  g_bp1[64];
__device__ float g_Wp2[54 * 128], g_bp2[128];
__device__ float g_Wp3[108 * 224], g_bp3[224];
__device__ float g_pool[NG * 216];
__device__ int   g_gcnt[NG];
__device__ int   g_goff[NG + 1];
__device__ float g_g1[NG * 1024];

// ---------------- preprocessing ----------------
__global__ void k_init() {
    int i = blockIdx.x * blockDim.x + threadIdx.x;
    if (i < NN) { g_cnt[i] = 1; g_fill[i] = 0; }   // 1 = self loop
    if (i < NG) g_gcnt[i] = 0;
}

__global__ void k_count(const int* __restrict__ ei) {
    int e = blockIdx.x * blockDim.x + threadIdx.x;
    if (e < NE) atomicAdd(&g_cnt[ei[NE + e]], 1);
}

__global__ void k_dinv() {
    int i = blockIdx.x * blockDim.x + threadIdx.x;
    if (i < NN) g_dinv[i] = rsqrtf((float)g_cnt[i]);
}

// single-block exclusive scan of g_cnt -> g_rowptr
__global__ void k_scan() {
    __shared__ int part[1024];
    const int CH = (NN + 1023) / 1024;
    int t = threadIdx.x;
    int lo = t * CH;
    int hi = min(lo + CH, NN);
    int s = 0;
    for (int i = lo; i < hi; i++) s += g_cnt[i];
    part[t] = s;
    __syncthreads();
    for (int off = 1; off < 1024; off <<= 1) {
        int v = (t >= off) ? part[t - off] : 0;
        __syncthreads();
        part[t] += v;
        __syncthreads();
    }
    int base = (t == 0) ? 0 : part[t - 1];
    for (int i = lo; i < hi; i++) { int c = g_cnt[i]; g_rowptr[i] = base; base += c; }
    if (t == 1023) g_rowptr[NN] = base;
}

__global__ void k_fill(const int* __restrict__ ei) {
    int i = blockIdx.x * blockDim.x + threadIdx.x;
    if (i >= NT_EDGE) return;
    int r, c;
    if (i < NE) { r = ei[i]; c = ei[NE + i]; }
    else        { r = c = i - NE; }
    float nrm = g_dinv[r] * g_dinv[c];
    int pos = g_rowptr[c] + atomicAdd(&g_fill[c], 1);
    g_edata[pos] = make_int2(r, __float_as_int(nrm));
}

// ---------------- aggregation: out[v] = sum_e norm_e * in[src_e] ----------
template <int F, int SIN, int SOUT>
__global__ void k_agg(const float* __restrict__ in, float* __restrict__ out) {
    int w = (blockIdx.x * blockDim.x + threadIdx.x) >> 5;
    int lane = threadIdx.x & 31;
    if (w >= NN) return;
    constexpr int J = (F + 31) / 32;
    float acc[J];
#pragma unroll
    for (int j = 0; j < J; j++) acc[j] = 0.f;
    int e0 = g_rowptr[w], e1 = g_rowptr[w + 1];
    int2 ed = (e0 < e1) ? g_edata[e0] : make_int2(0, 0);
    for (int e = e0; e < e1; e++) {
        int2 cur = ed;
        if (e + 1 < e1) ed = g_edata[e + 1];           // prefetch next edge
        float nrm = __int_as_float(cur.y);
        const float* src = in + (long)cur.x * SIN;
#pragma unroll
        for (int j = 0; j < J; j++) {
            int f = lane + 32 * j;
            if (f < F) acc[j] += nrm * __ldg(&src[f]);
        }
    }
    float* o = out + (long)w * SOUT;
#pragma unroll
    for (int j = 0; j < J; j++) {
        int f = lane + 32 * j;
        if (f < F) o[f] = acc[j];
    }
}

// ---------------- tiled SGEMM: out[N,CPAD] = relu(A[N,K]@W[K,CPAD] + b) ----
// TILE_M = 64 rows/block, thread tile 4 rows x 8 cols, BK = 16.
template <int K, int CPAD, bool RELU>
__global__ void k_gemm(const float* __restrict__ A, int sA,
                       const float* __restrict__ W, const float* __restrict__ b,
                       float* __restrict__ out) {
    constexpr int BK = 16;
    constexpr int NT = 16 * (CPAD / 8);
    __shared__ __align__(16) float Asm[BK][68];    // [k][row], padded row length
    __shared__ __align__(16) float Wsm[BK][CPAD];
    int tid = threadIdx.x;
    int rm = tid & 15;          // row group: rows rm*4 .. rm*4+3
    int cm = tid >> 4;          // col group: cols cm*8 .. cm*8+7
    int row0 = blockIdx.x * 64;
    float acc[4][8];
#pragma unroll
    for (int i = 0; i < 4; i++)
#pragma unroll
        for (int j = 0; j < 8; j++) acc[i][j] = 0.f;

    for (int k0 = 0; k0 < K; k0 += BK) {
        // stage A tile (transposed): kk fast for coalesced global read
        for (int i = tid; i < BK * 64; i += NT) {
            int kk = i & (BK - 1);
            int rr = i >> 4;
            int r = row0 + rr, k = k0 + kk;
            float v = 0.f;
            if (r < NN && k < K) v = A[(long)r * sA + k];
            Asm[kk][rr] = v;
        }
        // stage W tile
        for (int i = tid; i < BK * CPAD; i += NT) {
            int kk = i / CPAD, cc = i % CPAD;
            int k = k0 + kk;
            Wsm[kk][cc] = (k < K) ? W[k * CPAD + cc] : 0.f;
        }
        __syncthreads();
#pragma unroll
        for (int kk = 0; kk < BK; kk++) {
            float a0 = Asm[kk][rm * 4 + 0];
            float a1 = Asm[kk][rm * 4 + 1];
            float a2 = Asm[kk][rm * 4 + 2];
            float a3 = Asm[kk][rm * 4 + 3];
            float4 w0 = *(const float4*)&Wsm[kk][cm * 8];
            float4 w1 = *(const float4*)&Wsm[kk][cm * 8 + 4];
            float wv[8] = {w0.x, w0.y, w0.z, w0.w, w1.x, w1.y, w1.z, w1.w};
            float av[4] = {a0, a1, a2, a3};
#pragma unroll
            for (int i = 0; i < 4; i++)
#pragma unroll
                for (int j = 0; j < 8; j++) acc[i][j] += av[i] * wv[j];
        }
        __syncthreads();
    }
#pragma unroll
    for (int i = 0; i < 4; i++) {
        int r = row0 + rm * 4 + i;
        if (r >= NN) break;
#pragma unroll
        for (int j = 0; j < 8; j++) {
            int c = cm * 8 + j;
            float v = acc[i][j] + b[c];
            if (RELU) v = fmaxf(v, 0.f);
            out[(long)r * CPAD + c] = v;
        }
    }
}

// ---------------- weight/bias zero-padding ----------------
__global__ void k_padW(const float* __restrict__ W, const float* __restrict__ b,
                       float* __restrict__ Wp, float* __restrict__ bp,
                       int K, int C, int CPAD) {
    int i = blockIdx.x * blockDim.x + threadIdx.x;
    int tot = K * CPAD;
    if (i < tot) {
        int cc = i % CPAD, kk = i / CPAD;
        Wp[i] = (cc < C) ? W[kk * C + cc] : 0.f;
    } else if (i < tot + CPAD) {
        int cc = i - tot;
        bp[cc] = (cc < C) ? b[cc] : 0.f;
    }
}

// ---------------- pooling ----------------
__global__ void k_ghist(const int* __restrict__ batch) {
    int i = blockIdx.x * blockDim.x + threadIdx.x;
    if (i < NN) atomicAdd(&g_gcnt[batch[i]], 1);
}

__global__ void k_gscan() {   // 1 block, 256 threads
    __shared__ int p[NG];
    int t = threadIdx.x;
    p[t] = g_gcnt[t];
    __syncthreads();
    for (int off = 1; off < NG; off <<= 1) {
        int v = (t >= off) ? p[t - off] : 0;
        __syncthreads();
        p[t] += v;
        __syncthreads();
    }
    g_goff[t] = (t == 0) ? 0 : p[t - 1];
    if (t == NG - 1) g_goff[NG] = p[NG - 1];
}

__global__ void k_pool() {    // grid NG, block 224
    int g = blockIdx.x, f = threadIdx.x;
    if (f >= 216) return;
    int v0 = g_goff[g], v1 = g_goff[g + 1];
    float s = 0.f;
    for (int v = v0; v < v1; v++) s += g_h3[(long)v * 224 + f];
    float cnt = (float)(v1 - v0);
    g_pool[g * 216 + f] = s / fmaxf(cnt, 1.f);
}

// ---------------- MLP ----------------
__global__ void k_mlp1(const float* __restrict__ Wf1, const float* __restrict__ bf1) {
    __shared__ float ps[216];
    int g = blockIdx.x, t = threadIdx.x;       // 256 threads
    if (t < 216) ps[t] = g_pool[g * 216 + t];
    __syncthreads();
    float acc[4] = {0.f, 0.f, 0.f, 0.f};
    for (int k = 0; k < 216; k++) {
        float a = ps[k];
#pragma unroll
        for (int j = 0; j < 4; j++) acc[j] += a * Wf1[k * 1024 + t + 256 * j];
    }
#pragma unroll
    for (int j = 0; j < 4; j++) {
        int c = t + 256 * j;
        g_g1[g * 1024 + c] = fmaxf(acc[j] + bf1[c], 0.f);
    }
}

__global__ void k_mlp2(const float* __restrict__ Wf2, const float* __restrict__ bf2,
                       float* __restrict__ out) {
    __shared__ float ps[1024];
    int g = blockIdx.x, t = threadIdx.x;       // 128 threads
    for (int i = t; i < 1024; i += 128) ps[i] = g_g1[g * 1024 + i];
    __syncthreads();
    float acc = 0.f;
    for (int k = 0; k < 1024; k++) acc += ps[k] * Wf2[k * 128 + t];
    out[g * 128 + t] = acc + bf2[t];
}

// ---------------- launch ----------------
extern "C" void kernel_launch(void* const* d_in, const int* in_sizes, int n_in,
                              void* d_out, int out_size) {
    const float* x     = (const float*)d_in[0];
    const int*   ei    = (const int*)d_in[1];
    const int*   batch = (const int*)d_in[2];
    const float* W1 = (const float*)d_in[3];
    const float* b1 = (const float*)d_in[4];
    const float* W2 = (const float*)d_in[5];
    const float* b2 = (const float*)d_in[6];
    const float* W3 = (const float*)d_in[7];
    const float* b3 = (const float*)d_in[8];
    const float* Wf1 = (const float*)d_in[9];
    const float* bf1 = (const float*)d_in[10];
    const float* Wf2 = (const float*)d_in[11];
    const float* bf2 = (const float*)d_in[12];
    float* out = (float*)d_out;

    float *agg, *h1, *h2, *h3, *Wp1, *bp1, *Wp2, *bp2, *Wp3, *bp3;
    cudaGetSymbolAddress((void**)&agg, g_agg);
    cudaGetSymbolAddress((void**)&h1, g_h1);
    cudaGetSymbolAddress((void**)&h2, g_h2);
    cudaGetSymbolAddress((void**)&h3, g_h3);
    cudaGetSymbolAddress((void**)&Wp1, g_Wp1);
    cudaGetSymbolAddress((void**)&bp1, g_bp1);
    cudaGetSymbolAddress((void**)&Wp2, g_Wp2);
    cudaGetSymbolAddress((void**)&bp2, g_bp2);
    cudaGetSymbolAddress((void**)&Wp3, g_Wp3);
    cudaGetSymbolAddress((void**)&bp3, g_bp3);

    k_init<<<(NN + 255) / 256, 256>>>();
    k_padW<<<(54 * 64 + 64 + 255) / 256, 256>>>(W1, b1, Wp1, bp1, 54, 54, 64);
    k_padW<<<(54 * 128 + 128 + 255) / 256, 256>>>(W2, b2, Wp2, bp2, 54, 108, 128);
    k_padW<<<(108 * 224 + 224 + 255) / 256, 256>>>(W3, b3, Wp3, bp3, 108, 216, 224);
    k_count<<<(NE + 255) / 256, 256>>>(ei);
    k_dinv<<<(NN + 255) / 256, 256>>>();
    k_scan<<<1, 1024>>>();
    k_fill<<<(NT_EDGE + 255) / 256, 256>>>(ei);
    k_ghist<<<(NN + 255) / 256, 256>>>(batch);
    k_gscan<<<1, NG>>>();

    // layer 1: aggregate x (F=54), then GEMM 54 -> 64(pad of 54) + relu
    k_agg<54, 54, 54><<<(NN * 32 + 255) / 256, 256>>>(x, agg);
    k_gemm<54, 64, true><<<(NN + 63) / 64, 128>>>(agg, 54, Wp1, bp1, h1);
    // layer 2: aggregate h1 (F=54, stride 64), GEMM 54 -> 128(pad of 108) + relu
    k_agg<54, 64, 54><<<(NN * 32 + 255) / 256, 256>>>(h1, agg);
    k_gemm<54, 128, true><<<(NN + 63) / 64, 256>>>(agg, 54, Wp2, bp2, h2);
    // layer 3: aggregate h2 (F=108, stride 128), GEMM 108 -> 224(pad of 216) + relu
    k_agg<108, 128, 108><<<(NN * 32 + 255) / 256, 256>>>(h2, agg);
    k_gemm<108, 224, true><<<(NN + 63) / 64, 448>>>(agg, 108, Wp3, bp3, h3);

    k_pool<<<NG, 224>>>();
    k_mlp1<<<NG, 256>>>(Wf1, bf1);
    k_mlp2<<<NG, 128>>>(Wf2, bf2, out);
}

// round 3
// speedup vs baseline: 1.4828x; 1.4828x over previous
#include <cuda_runtime.h>

#define NN 100000
#define NE 1600000
#define NT_EDGE 1700000   // edges + self loops
#define NG 256

// ---------------- scratch (static device allocations; no runtime alloc) ----
__device__ int   g_cnt[NN];
__device__ int   g_fill[NN];
__device__ float g_dinv[NN];
__device__ int   g_rowptr[NN + 1];
__device__ int2  g_edata[NT_EDGE];          // {src, float_as_int(norm)} bucketed by dst
__device__ float g_agg[NN * 112];           // aggregation output (max padded width 112)
__device__ float g_h1[NN * 64];             // layer1 out, 54 real cols, stride 64
__device__ float g_h2[NN * 128];            // layer2 out, 108 real cols, stride 128
__device__ float g_h3[NN * 224];            // layer3 out, 216 real cols, stride 224
__device__ float g_Wp1[56 * 64],   g_bp1[64];
__device__ float g_Wp2[56 * 128],  g_bp2[128];
__device__ float g_Wp3[112 * 224], g_bp3[224];
__device__ float g_pool[NG * 216];
__device__ int   g_gcnt[NG];
__device__ int   g_goff[NG + 1];
__device__ float g_g1[NG * 1024];

// ---------------- preprocessing ----------------
__global__ void k_init() {
    int i = blockIdx.x * blockDim.x + threadIdx.x;
    if (i < NN) { g_cnt[i] = 1; g_fill[i] = 0; }   // 1 = self loop
    if (i < NG) g_gcnt[i] = 0;
}

__global__ void k_count(const int* __restrict__ ei) {
    int e = blockIdx.x * blockDim.x + threadIdx.x;
    if (e < NE) atomicAdd(&g_cnt[ei[NE + e]], 1);
}

__global__ void k_dinv() {
    int i = blockIdx.x * blockDim.x + threadIdx.x;
    if (i < NN) g_dinv[i] = rsqrtf((float)g_cnt[i]);
}

// single-block exclusive scan of g_cnt -> g_rowptr
__global__ void k_scan() {
    __shared__ int part[1024];
    const int CH = (NN + 1023) / 1024;
    int t = threadIdx.x;
    int lo = t * CH;
    int hi = min(lo + CH, NN);
    int s = 0;
    for (int i = lo; i < hi; i++) s += g_cnt[i];
    part[t] = s;
    __syncthreads();
    for (int off = 1; off < 1024; off <<= 1) {
        int v = (t >= off) ? part[t - off] : 0;
        __syncthreads();
        part[t] += v;
        __syncthreads();
    }
    int base = (t == 0) ? 0 : part[t - 1];
    for (int i = lo; i < hi; i++) { int c = g_cnt[i]; g_rowptr[i] = base; base += c; }
    if (t == 1023) g_rowptr[NN] = base;
}

__global__ void k_fill(const int* __restrict__ ei) {
    int i = blockIdx.x * blockDim.x + threadIdx.x;
    if (i >= NT_EDGE) return;
    int r, c;
    if (i < NE) { r = ei[i]; c = ei[NE + i]; }
    else        { r = c = i - NE; }
    float nrm = g_dinv[r] * g_dinv[c];
    int pos = g_rowptr[c] + atomicAdd(&g_fill[c], 1);
    g_edata[pos] = make_int2(r, __float_as_int(nrm));
}

// ---------------- aggregation: out[v] = sum_e norm_e * in[src_e] ----------
// Output rows padded to SOUT with zeros (zeros feed the padded GEMM K dim).
template <int F, int SIN, int SOUT>
__global__ void k_agg(const float* __restrict__ in, float* __restrict__ out) {
    int w = (blockIdx.x * blockDim.x + threadIdx.x) >> 5;
    int lane = threadIdx.x & 31;
    if (w >= NN) return;
    constexpr int J = (F + 31) / 32;
    constexpr int JW = (SOUT + 31) / 32;
    static_assert(JW == J, "pad within last warp chunk");
    float acc[J];
#pragma unroll
    for (int j = 0; j < J; j++) acc[j] = 0.f;
    int e0 = g_rowptr[w], e1 = g_rowptr[w + 1];
    int2 ed = (e0 < e1) ? g_edata[e0] : make_int2(0, 0);
    for (int e = e0; e < e1; e++) {
        int2 cur = ed;
        if (e + 1 < e1) ed = g_edata[e + 1];           // prefetch next edge
        float nrm = __int_as_float(cur.y);
        const float* src = in + (long)cur.x * SIN;
#pragma unroll
        for (int j = 0; j < J; j++) {
            int f = lane + 32 * j;
            if (f < F) acc[j] += nrm * __ldg(&src[f]);
        }
    }
    float* o = out + (long)w * SOUT;
#pragma unroll
    for (int j = 0; j < J; j++) {
        int f = lane + 32 * j;
        if (f < SOUT) o[f] = (f < F) ? acc[j] : 0.f;
    }
}

// ---------------- tf32 tensor-core GEMM ----------------
// out[N, CPAD] = relu(A[N, KPAD] @ W[KPAD, CPAD] + b), A rows contiguous
// (stride == KPAD, zero-padded), W zero-padded to KPAD x CPAD.
// Block: 256 threads = 8 warps = 2 (M) x 4 (N); block tile 64 x CPAD.
// Warp tile: 32 rows (2 m16 tiles) x CPAD/4 cols (CPAD/32 n8 tiles).

__device__ __forceinline__ unsigned f2tf(float v) {
    unsigned u;
    asm("cvt.rna.tf32.f32 %0, %1;" : "=r"(u) : "f"(v));
    return u;
}

__device__ __forceinline__ void mma_tf32(float c[4], const unsigned a[4], const unsigned b[2]) {
    asm volatile(
        "mma.sync.aligned.m16n8k8.row.col.f32.tf32.tf32.f32 "
        "{%0,%1,%2,%3}, {%4,%5,%6,%7}, {%8,%9}, {%0,%1,%2,%3};\n"
        : "+f"(c[0]), "+f"(c[1]), "+f"(c[2]), "+f"(c[3])
        : "r"(a[0]), "r"(a[1]), "r"(a[2]), "r"(a[3]), "r"(b[0]), "r"(b[1]));
}

template <int KPAD, int CPAD>
__global__ __launch_bounds__(256)
void k_gemm_mma(const float* __restrict__ A, const float* __restrict__ W,
                const float* __restrict__ bias, float* __restrict__ out) {
    extern __shared__ float sm[];
    constexpr int ASTR = KPAD + 2;
    constexpr int WSTR = CPAD + 8;        // stride % 32 == 8 -> conflict-free B frags
    constexpr int KCH = 56;               // K chunk rows staged at a time
    constexpr int NTILES = CPAD / 32;     // n8 tiles per warp
    float* As = sm;                       // [64][ASTR]
    float* Ws = sm + 64 * ASTR;           // [KCH][WSTR]

    int tid = threadIdx.x;
    int w = tid >> 5, lane = tid & 31;
    int g = lane >> 2, ctg = lane & 3;
    int wm = w & 1, wn = w >> 1;
    int row0 = blockIdx.x * 64;

    float c[2][NTILES][4];
#pragma unroll
    for (int mt = 0; mt < 2; mt++)
#pragma unroll
        for (int nt = 0; nt < NTILES; nt++)
#pragma unroll
            for (int i = 0; i < 4; i++) c[mt][nt][i] = 0.f;

    // stage A (full K), convert to tf32
    for (int i = tid * 4; i < 64 * KPAD; i += 256 * 4) {
        int r = i / KPAD, k = i % KPAD;
        float4 v = make_float4(0.f, 0.f, 0.f, 0.f);
        if (row0 + r < NN) v = *(const float4*)&A[(long)(row0 + r) * KPAD + k];
        As[r * ASTR + k + 0] = __uint_as_float(f2tf(v.x));
        As[r * ASTR + k + 1] = __uint_as_float(f2tf(v.y));
        As[r * ASTR + k + 2] = __uint_as_float(f2tf(v.z));
        As[r * ASTR + k + 3] = __uint_as_float(f2tf(v.w));
    }

#pragma unroll 1
    for (int kc = 0; kc < KPAD; kc += KCH) {
        constexpr int kchunk = (KPAD < KCH) ? KPAD : KCH;  // KPAD is 56 or 112
        // stage W chunk
        for (int i = tid * 4; i < kchunk * CPAD; i += 256 * 4) {
            int kk = i / CPAD, cc = i % CPAD;
            float4 v = *(const float4*)&W[(long)(kc + kk) * CPAD + cc];
            float4 t;
            t.x = __uint_as_float(f2tf(v.x));
            t.y = __uint_as_float(f2tf(v.y));
            t.z = __uint_as_float(f2tf(v.z));
            t.w = __uint_as_float(f2tf(v.w));
            *(float4*)&Ws[kk * WSTR + cc] = t;
        }
        __syncthreads();

#pragma unroll
        for (int ks = 0; ks < kchunk; ks += 8) {
            unsigned a[2][4];
#pragma unroll
            for (int mt = 0; mt < 2; mt++) {
                int ar = wm * 32 + mt * 16;
                int kb = kc + ks + ctg;
                a[mt][0] = __float_as_uint(As[(ar + g) * ASTR + kb]);
                a[mt][1] = __float_as_uint(As[(ar + g + 8) * ASTR + kb]);
                a[mt][2] = __float_as_uint(As[(ar + g) * ASTR + kb + 4]);
                a[mt][3] = __float_as_uint(As[(ar + g + 8) * ASTR + kb + 4]);
            }
            unsigned b[NTILES][2];
#pragma unroll
            for (int nt = 0; nt < NTILES; nt++) {
                int col = wn * (CPAD / 4) + nt * 8 + g;
                b[nt][0] = __float_as_uint(Ws[(ks + ctg) * WSTR + col]);
                b[nt][1] = __float_as_uint(Ws[(ks + ctg + 4) * WSTR + col]);
            }
#pragma unroll
            for (int mt = 0; mt < 2; mt++)
#pragma unroll
                for (int nt = 0; nt < NTILES; nt++)
                    mma_tf32(c[mt][nt], a[mt], b[nt]);
        }
        __syncthreads();
    }

    // epilogue: bias + relu, write float2 per fragment half
#pragma unroll
    for (int mt = 0; mt < 2; mt++) {
        int r0 = row0 + wm * 32 + mt * 16 + g;
#pragma unroll
        for (int nt = 0; nt < NTILES; nt++) {
            int col = wn * (CPAD / 4) + nt * 8 + 2 * ctg;
            float b0 = bias[col], b1 = bias[col + 1];
            if (r0 < NN) {
                float2 v;
                v.x = fmaxf(c[mt][nt][0] + b0, 0.f);
                v.y = fmaxf(c[mt][nt][1] + b1, 0.f);
                *(float2*)&out[(long)r0 * CPAD + col] = v;
            }
            if (r0 + 8 < NN) {
                float2 v;
                v.x = fmaxf(c[mt][nt][2] + b0, 0.f);
                v.y = fmaxf(c[mt][nt][3] + b1, 0.f);
                *(float2*)&out[(long)(r0 + 8) * CPAD + col] = v;
            }
        }
    }
}

// ---------------- weight/bias zero-padding ----------------
__global__ void k_padW(const float* __restrict__ W, const float* __restrict__ b,
                       float* __restrict__ Wp, float* __restrict__ bp,
                       int K, int C, int KPAD, int CPAD) {
    int i = blockIdx.x * blockDim.x + threadIdx.x;
    int tot = KPAD * CPAD;
    if (i < tot) {
        int cc = i % CPAD, kk = i / CPAD;
        Wp[i] = (cc < C && kk < K) ? W[kk * C + cc] : 0.f;
    } else if (i < tot + CPAD) {
        int cc = i - tot;
        bp[cc] = (cc < C) ? b[cc] : 0.f;
    }
}

// ---------------- pooling ----------------
__global__ void k_ghist(const int* __restrict__ batch) {
    int i = blockIdx.x * blockDim.x + threadIdx.x;
    if (i < NN) atomicAdd(&g_gcnt[batch[i]], 1);
}

__global__ void k_gscan() {   // 1 block, 256 threads
    __shared__ int p[NG];
    int t = threadIdx.x;
    p[t] = g_gcnt[t];
    __syncthreads();
    for (int off = 1; off < NG; off <<= 1) {
        int v = (t >= off) ? p[t - off] : 0;
        __syncthreads();
        p[t] += v;
        __syncthreads();
    }
    g_goff[t] = (t == 0) ? 0 : p[t - 1];
    if (t == NG - 1) g_goff[NG] = p[NG - 1];
}

__global__ void k_pool() {    // grid NG, block 224
    int g = blockIdx.x, f = threadIdx.x;
    if (f >= 216) return;
    int v0 = g_goff[g], v1 = g_goff[g + 1];
    float s = 0.f;
    for (int v = v0; v < v1; v++) s += g_h3[(long)v * 224 + f];
    float cnt = (float)(v1 - v0);
    g_pool[g * 216 + f] = s / fmaxf(cnt, 1.f);
}

// ---------------- MLP (fp32) ----------------
__global__ void k_mlp1(const float* __restrict__ Wf1, const float* __restrict__ bf1) {
    __shared__ float ps[216];
    int g = blockIdx.x, t = threadIdx.x;       // 256 threads
    if (t < 216) ps[t] = g_pool[g * 216 + t];
    __syncthreads();
    float acc[4] = {0.f, 0.f, 0.f, 0.f};
    for (int k = 0; k < 216; k++) {
        float a = ps[k];
#pragma unroll
        for (int j = 0; j < 4; j++) acc[j] += a * Wf1[k * 1024 + t + 256 * j];
    }
#pragma unroll
    for (int j = 0; j < 4; j++) {
        int c = t + 256 * j;
        g_g1[g * 1024 + c] = fmaxf(acc[j] + bf1[c], 0.f);
    }
}

__global__ void k_mlp2(const float* __restrict__ Wf2, const float* __restrict__ bf2,
                       float* __restrict__ out) {
    __shared__ float ps[1024];
    int g = blockIdx.x, t = threadIdx.x;       // 128 threads
    for (int i = t; i < 1024; i += 128) ps[i] = g_g1[g * 1024 + i];
    __syncthreads();
    float acc = 0.f;
    for (int k = 0; k < 1024; k++) acc += ps[k] * Wf2[k * 128 + t];
    out[g * 128 + t] = acc + bf2[t];
}

// ---------------- launch ----------------
static int smem_bytes(int KPAD, int CPAD) {
    return (64 * (KPAD + 2) + 56 * (CPAD + 8)) * 4;
}

extern "C" void kernel_launch(void* const* d_in, const int* in_sizes, int n_in,
                              void* d_out, int out_size) {
    const float* x     = (const float*)d_in[0];
    const int*   ei    = (const int*)d_in[1];
    const int*   batch = (const int*)d_in[2];
    const float* W1 = (const float*)d_in[3];
    const float* b1 = (const float*)d_in[4];
    const float* W2 = (const float*)d_in[5];
    const float* b2 = (const float*)d_in[6];
    const float* W3 = (const float*)d_in[7];
    const float* b3 = (const float*)d_in[8];
    const float* Wf1 = (const float*)d_in[9];
    const float* bf1 = (const float*)d_in[10];
    const float* Wf2 = (const float*)d_in[11];
    const float* bf2 = (const float*)d_in[12];
    float* out = (float*)d_out;

    float *agg, *h1, *h2, *h3, *Wp1, *bp1, *Wp2, *bp2, *Wp3, *bp3;
    cudaGetSymbolAddress((void**)&agg, g_agg);
    cudaGetSymbolAddress((void**)&h1, g_h1);
    cudaGetSymbolAddress((void**)&h2, g_h2);
    cudaGetSymbolAddress((void**)&h3, g_h3);
    cudaGetSymbolAddress((void**)&Wp1, g_Wp1);
    cudaGetSymbolAddress((void**)&bp1, g_bp1);
    cudaGetSymbolAddress((void**)&Wp2, g_Wp2);
    cudaGetSymbolAddress((void**)&bp2, g_bp2);
    cudaGetSymbolAddress((void**)&Wp3, g_Wp3);
    cudaGetSymbolAddress((void**)&bp3, g_bp3);

    // idempotent, non-stream API calls (no static guard; legal during capture)
    cudaFuncSetAttribute(k_gemm_mma<56, 64>,
                         cudaFuncAttributeMaxDynamicSharedMemorySize, smem_bytes(56, 64));
    cudaFuncSetAttribute(k_gemm_mma<56, 128>,
                         cudaFuncAttributeMaxDynamicSharedMemorySize, smem_bytes(56, 128));
    cudaFuncSetAttribute(k_gemm_mma<112, 224>,
                         cudaFuncAttributeMaxDynamicSharedMemorySize, smem_bytes(112, 224));

    k_init<<<(NN + 255) / 256, 256>>>();
    k_padW<<<(56 * 64 + 64 + 255) / 256, 256>>>(W1, b1, Wp1, bp1, 54, 54, 56, 64);
    k_padW<<<(56 * 128 + 128 + 255) / 256, 256>>>(W2, b2, Wp2, bp2, 54, 108, 56, 128);
    k_padW<<<(112 * 224 + 224 + 255) / 256, 256>>>(W3, b3, Wp3, bp3, 108, 216, 112, 224);
    k_count<<<(NE + 255) / 256, 256>>>(ei);
    k_dinv<<<(NN + 255) / 256, 256>>>();
    k_scan<<<1, 1024>>>();
    k_fill<<<(NT_EDGE + 255) / 256, 256>>>(ei);
    k_ghist<<<(NN + 255) / 256, 256>>>(batch);
    k_gscan<<<1, NG>>>();

    int gblk = (NN + 63) / 64;
    // layer 1: aggregate x (F=54 -> pad 56), GEMM 56 -> 64(pad of 54) + relu
    k_agg<54, 54, 56><<<(NN * 32 + 255) / 256, 256>>>(x, agg);
    k_gemm_mma<56, 64><<<gblk, 256, smem_bytes(56, 64)>>>(agg, Wp1, bp1, h1);
    // layer 2: aggregate h1 (F=54, stride 64 -> pad 56), GEMM 56 -> 128(pad of 108) + relu
    k_agg<54, 64, 56><<<(NN * 32 + 255) / 256, 256>>>(h1, agg);
    k_gemm_mma<56, 128><<<gblk, 256, smem_bytes(56, 128)>>>(agg, Wp2, bp2, h2);
    // layer 3: aggregate h2 (F=108, stride 128 -> pad 112), GEMM 112 -> 224(pad of 216) + relu
    k_agg<108, 128, 112><<<(NN * 32 + 255) / 256, 256>>>(h2, agg);
    k_gemm_mma<112, 224><<<gblk, 256, smem_bytes(112, 224)>>>(agg, Wp3, bp3, h3);

    k_pool<<<NG, 224>>>();
    k_mlp1<<<NG, 256>>>(Wf1, bf1);
    k_mlp2<<<NG, 128>>>(Wf2, bf2, out);
}

// round 4
// speedup vs baseline: 1.4930x; 1.0069x over previous
#include <cuda_runtime.h>

#define NN 100000
#define NE 1600000
#define NT_EDGE 1700000   // edges + self loops
#define NG 256

// ---------------- scratch (static device allocations; no runtime alloc) ----
__device__ int   g_cnt[NN];
__device__ int   g_fill[NN];
__device__ int   g_rowptr[NN + 1];
__device__ __align__(16) int2  g_edata[NT_EDGE];   // {src, f2i(norm)} bucketed by dst
__device__ __align__(16) float g_xp[NN * 56];      // x padded to stride 56
__device__ __align__(16) float g_agg[NN * 112];    // aggregation out (max padded 112)
__device__ __align__(16) float g_h1[NN * 64];      // layer1 out, 54 real, stride 64
__device__ __align__(16) float g_h2[NN * 128];     // layer2 out, 108 real, stride 128
__device__ __align__(16) float g_h3[NN * 224];     // layer3 out, 216 real, stride 224
__device__ __align__(16) float g_Wp1[56 * 64];
__device__ __align__(16) float g_Wp2[56 * 128];
__device__ __align__(16) float g_Wp3[112 * 224];
__device__ float g_bp1[64], g_bp2[128], g_bp3[224];
__device__ float g_pool[NG * 216];
__device__ int   g_gcnt[NG];
__device__ int   g_goff[NG + 1];
__device__ float g_g1[NG * 1024];

// ---------------- fused setup: init + gcnt + padW x3 + x padding ----------
#define PW1 (56 * 64 + 64)
#define PW2 (56 * 128 + 128)
#define PW3 (112 * 224 + 224)
#define S0 NN
#define S1 (S0 + NG)
#define S2 (S1 + PW1)
#define S3 (S2 + PW2)
#define S4 (S3 + PW3)
#define S5 (S4 + NN * 56)

__device__ __forceinline__ void padw_one(int j, const float* W, const float* b,
                                         float* Wp, float* bp, int K, int C,
                                         int KPAD, int CPAD) {
    int tot = KPAD * CPAD;
    if (j < tot) {
        int cc = j % CPAD, kk = j / CPAD;
        Wp[j] = (cc < C && kk < K) ? W[kk * C + cc] : 0.f;
    } else {
        int cc = j - tot;
        bp[cc] = (cc < C) ? b[cc] : 0.f;
    }
}

__global__ void k_setup(const float* __restrict__ x,
                        const float* __restrict__ W1, const float* __restrict__ b1,
                        const float* __restrict__ W2, const float* __restrict__ b2,
                        const float* __restrict__ W3, const float* __restrict__ b3) {
    int i = blockIdx.x * blockDim.x + threadIdx.x;
    if (i < S0) {
        g_cnt[i] = 1;              // self loop
        g_fill[i] = 0;
    } else if (i < S1) {
        g_gcnt[i - S0] = 0;
    } else if (i < S2) {
        padw_one(i - S1, W1, b1, g_Wp1, g_bp1, 54, 54, 56, 64);
    } else if (i < S3) {
        padw_one(i - S2, W2, b2, g_Wp2, g_bp2, 54, 108, 56, 128);
    } else if (i < S4) {
        padw_one(i - S3, W3, b3, g_Wp3, g_bp3, 108, 216, 112, 224);
    } else if (i < S5) {
        int j = i - S4;
        int r = j / 56, c = j - r * 56;
        g_xp[j] = (c < 54) ? x[r * 54 + c] : 0.f;
    }
}

// ---------------- preprocessing ----------------
__global__ void k_count(const int* __restrict__ ei) {
    int e = blockIdx.x * blockDim.x + threadIdx.x;
    if (e < NE) atomicAdd(&g_cnt[ei[NE + e]], 1);
}

// single-block exclusive scan of g_cnt -> g_rowptr
__global__ void k_scan() {
    __shared__ int part[1024];
    const int CH = (NN + 1023) / 1024;
    int t = threadIdx.x;
    int lo = t * CH;
    int hi = min(lo + CH, NN);
    int s = 0;
    for (int i = lo; i < hi; i++) s += g_cnt[i];
    part[t] = s;
    __syncthreads();
    for (int off = 1; off < 1024; off <<= 1) {
        int v = (t >= off) ? part[t - off] : 0;
        __syncthreads();
        part[t] += v;
        __syncthreads();
    }
    int base = (t == 0) ? 0 : part[t - 1];
    for (int i = lo; i < hi; i++) { int c = g_cnt[i]; g_rowptr[i] = base; base += c; }
    if (t == 1023) g_rowptr[NN] = base;
}

__global__ void k_fill(const int* __restrict__ ei) {
    int i = blockIdx.x * blockDim.x + threadIdx.x;
    if (i >= NT_EDGE) return;
    int r, c;
    if (i < NE) { r = ei[i]; c = ei[NE + i]; }
    else        { r = c = i - NE; }
    float nrm = rsqrtf((float)g_cnt[r] * (float)g_cnt[c]);
    int pos = g_rowptr[c] + atomicAdd(&g_fill[c], 1);
    g_edata[pos] = make_int2(r, __float_as_int(nrm));
}

// ---------------- aggregation (vectorized) ----------------
// Rows of `in` are 16B-aligned; 14 float4 = 56 floats per row.
// Two edges per warp: lanes 0-13 edge e, lanes 16-29 edge e+1.
template <int SIN>   // input row stride in floats (56 or 64)
__global__ void k_agg56(const float* __restrict__ in, float* __restrict__ out) {
    int w = (blockIdx.x * blockDim.x + threadIdx.x) >> 5;
    int lane = threadIdx.x & 31;
    if (w >= NN) return;
    int half = lane >> 4, sl = lane & 15;
    bool act = sl < 14;
    int e0 = g_rowptr[w], e1 = g_rowptr[w + 1];
    float4 acc = make_float4(0.f, 0.f, 0.f, 0.f);
    for (int e = e0; e < e1; e += 2) {
        int idx = e + half;
        bool v = idx < e1;
        int2 ed = __ldg(&g_edata[v ? idx : e]);
        float nrm = v ? __int_as_float(ed.y) : 0.f;
        if (act) {
            const float4* src = (const float4*)(in + (long)ed.x * SIN);
            float4 t = __ldg(&src[sl]);
            acc.x += nrm * t.x; acc.y += nrm * t.y;
            acc.z += nrm * t.z; acc.w += nrm * t.w;
        }
    }
    acc.x += __shfl_xor_sync(0xffffffffu, acc.x, 16);
    acc.y += __shfl_xor_sync(0xffffffffu, acc.y, 16);
    acc.z += __shfl_xor_sync(0xffffffffu, acc.z, 16);
    acc.w += __shfl_xor_sync(0xffffffffu, acc.w, 16);
    if (half == 0 && act)
        ((float4*)(out + (long)w * 56))[sl] = acc;
}

// 112-float rows (28 float4 lanes), one edge per warp. in = h2, stride 128.
__global__ void k_agg112(const float* __restrict__ in, float* __restrict__ out) {
    int w = (blockIdx.x * blockDim.x + threadIdx.x) >> 5;
    int lane = threadIdx.x & 31;
    if (w >= NN) return;
    bool act = lane < 28;
    int e0 = g_rowptr[w], e1 = g_rowptr[w + 1];
    float4 acc = make_float4(0.f, 0.f, 0.f, 0.f);
    for (int e = e0; e < e1; e++) {
        int2 ed = __ldg(&g_edata[e]);
        float nrm = __int_as_float(ed.y);
        if (act) {
            const float4* src = (const float4*)(in + (long)ed.x * 128);
            float4 t = __ldg(&src[lane]);
            acc.x += nrm * t.x; acc.y += nrm * t.y;
            acc.z += nrm * t.z; acc.w += nrm * t.w;
        }
    }
    if (act)
        ((float4*)(out + (long)w * 112))[lane] = acc;
}

// ---------------- tf32 tensor-core GEMM ----------------
__device__ __forceinline__ unsigned f2tf(float v) {
    unsigned u;
    asm("cvt.rna.tf32.f32 %0, %1;" : "=r"(u) : "f"(v));
    return u;
}

__device__ __forceinline__ void mma_tf32(float c[4], const unsigned a[4], const unsigned b[2]) {
    asm volatile(
        "mma.sync.aligned.m16n8k8.row.col.f32.tf32.tf32.f32 "
        "{%0,%1,%2,%3}, {%4,%5,%6,%7}, {%8,%9}, {%0,%1,%2,%3};\n"
        : "+f"(c[0]), "+f"(c[1]), "+f"(c[2]), "+f"(c[3])
        : "r"(a[0]), "r"(a[1]), "r"(a[2]), "r"(a[3]), "r"(b[0]), "r"(b[1]));
}

template <int KPAD, int CPAD>
__global__ __launch_bounds__(256)
void k_gemm_mma(const float* __restrict__ A, const float* __restrict__ W,
                const float* __restrict__ bias, float* __restrict__ out) {
    extern __shared__ float sm[];
    constexpr int ASTR = KPAD + 2;
    constexpr int WSTR = CPAD + 8;
    constexpr int KCH = 56;
    constexpr int NTILES = CPAD / 32;
    float* As = sm;                       // [64][ASTR]
    float* Ws = sm + 64 * ASTR;           // [KCH][WSTR]

    int tid = threadIdx.x;
    int w = tid >> 5, lane = tid & 31;
    int g = lane >> 2, ctg = lane & 3;
    int wm = w & 1, wn = w >> 1;
    int row0 = blockIdx.x * 64;

    float c[2][NTILES][4];
#pragma unroll
    for (int mt = 0; mt < 2; mt++)
#pragma unroll
        for (int nt = 0; nt < NTILES; nt++)
#pragma unroll
            for (int i = 0; i < 4; i++) c[mt][nt][i] = 0.f;

    for (int i = tid * 4; i < 64 * KPAD; i += 256 * 4) {
        int r = i / KPAD, k = i % KPAD;
        float4 v = make_float4(0.f, 0.f, 0.f, 0.f);
        if (row0 + r < NN) v = *(const float4*)&A[(long)(row0 + r) * KPAD + k];
        As[r * ASTR + k + 0] = __uint_as_float(f2tf(v.x));
        As[r * ASTR + k + 1] = __uint_as_float(f2tf(v.y));
        As[r * ASTR + k + 2] = __uint_as_float(f2tf(v.z));
        As[r * ASTR + k + 3] = __uint_as_float(f2tf(v.w));
    }

#pragma unroll 1
    for (int kc = 0; kc < KPAD; kc += KCH) {
        constexpr int kchunk = (KPAD < KCH) ? KPAD : KCH;
        for (int i = tid * 4; i < kchunk * CPAD; i += 256 * 4) {
            int kk = i / CPAD, cc = i % CPAD;
            float4 v = *(const float4*)&W[(long)(kc + kk) * CPAD + cc];
            float4 t;
            t.x = __uint_as_float(f2tf(v.x));
            t.y = __uint_as_float(f2tf(v.y));
            t.z = __uint_as_float(f2tf(v.z));
            t.w = __uint_as_float(f2tf(v.w));
            *(float4*)&Ws[kk * WSTR + cc] = t;
        }
        __syncthreads();

#pragma unroll
        for (int ks = 0; ks < kchunk; ks += 8) {
            unsigned a[2][4];
#pragma unroll
            for (int mt = 0; mt < 2; mt++) {
                int ar = wm * 32 + mt * 16;
                int kb = kc + ks + ctg;
                a[mt][0] = __float_as_uint(As[(ar + g) * ASTR + kb]);
                a[mt][1] = __float_as_uint(As[(ar + g + 8) * ASTR + kb]);
                a[mt][2] = __float_as_uint(As[(ar + g) * ASTR + kb + 4]);
                a[mt][3] = __float_as_uint(As[(ar + g + 8) * ASTR + kb + 4]);
            }
            unsigned b[NTILES][2];
#pragma unroll
            for (int nt = 0; nt < NTILES; nt++) {
                int col = wn * (CPAD / 4) + nt * 8 + g;
                b[nt][0] = __float_as_uint(Ws[(ks + ctg) * WSTR + col]);
                b[nt][1] = __float_as_uint(Ws[(ks + ctg + 4) * WSTR + col]);
            }
#pragma unroll
            for (int mt = 0; mt < 2; mt++)
#pragma unroll
                for (int nt = 0; nt < NTILES; nt++)
                    mma_tf32(c[mt][nt], a[mt], b[nt]);
        }
        __syncthreads();
    }

#pragma unroll
    for (int mt = 0; mt < 2; mt++) {
        int r0 = row0 + wm * 32 + mt * 16 + g;
#pragma unroll
        for (int nt = 0; nt < NTILES; nt++) {
            int col = wn * (CPAD / 4) + nt * 8 + 2 * ctg;
            float b0 = bias[col], b1 = bias[col + 1];
            if (r0 < NN) {
                float2 v;
                v.x = fmaxf(c[mt][nt][0] + b0, 0.f);
                v.y = fmaxf(c[mt][nt][1] + b1, 0.f);
                *(float2*)&out[(long)r0 * CPAD + col] = v;
            }
            if (r0 + 8 < NN) {
                float2 v;
                v.x = fmaxf(c[mt][nt][2] + b0, 0.f);
                v.y = fmaxf(c[mt][nt][3] + b1, 0.f);
                *(float2*)&out[(long)(r0 + 8) * CPAD + col] = v;
            }
        }
    }
}

// ---------------- pooling ----------------
__global__ void k_ghist(const int* __restrict__ batch) {
    int i = blockIdx.x * blockDim.x + threadIdx.x;
    if (i < NN) atomicAdd(&g_gcnt[batch[i]], 1);
}

__global__ void k_gscan() {   // 1 block, 256 threads
    __shared__ int p[NG];
    int t = threadIdx.x;
    p[t] = g_gcnt[t];
    __syncthreads();
    for (int off = 1; off < NG; off <<= 1) {
        int v = (t >= off) ? p[t - off] : 0;
        __syncthreads();
        p[t] += v;
        __syncthreads();
    }
    g_goff[t] = (t == 0) ? 0 : p[t - 1];
    if (t == NG - 1) g_goff[NG] = p[NG - 1];
}

__global__ void k_pool() {    // grid NG, block 224
    int g = blockIdx.x, f = threadIdx.x;
    if (f >= 216) return;
    int v0 = g_goff[g], v1 = g_goff[g + 1];
    float s = 0.f;
    for (int v = v0; v < v1; v++) s += g_h3[(long)v * 224 + f];
    float cnt = (float)(v1 - v0);
    g_pool[g * 216 + f] = s / fmaxf(cnt, 1.f);
}

// ---------------- MLP (fp32) ----------------
__global__ void k_mlp1(const float* __restrict__ Wf1, const float* __restrict__ bf1) {
    __shared__ float ps[216];
    int g = blockIdx.x, t = threadIdx.x;       // 256 threads
    if (t < 216) ps[t] = g_pool[g * 216 + t];
    __syncthreads();
    float acc[4] = {0.f, 0.f, 0.f, 0.f};
    for (int k = 0; k < 216; k++) {
        float a = ps[k];
#pragma unroll
        for (int j = 0; j < 4; j++) acc[j] += a * Wf1[k * 1024 + t + 256 * j];
    }
#pragma unroll
    for (int j = 0; j < 4; j++) {
        int c = t + 256 * j;
        g_g1[g * 1024 + c] = fmaxf(acc[j] + bf1[c], 0.f);
    }
}

__global__ void k_mlp2(const float* __restrict__ Wf2, const float* __restrict__ bf2,
                       float* __restrict__ out) {
    __shared__ float ps[1024];
    int g = blockIdx.x, t = threadIdx.x;       // 128 threads
    for (int i = t; i < 1024; i += 128) ps[i] = g_g1[g * 1024 + i];
    __syncthreads();
    float acc = 0.f;
    for (int k = 0; k < 1024; k++) acc += ps[k] * Wf2[k * 128 + t];
    out[g * 128 + t] = acc + bf2[t];
}

// ---------------- launch ----------------
static int smem_bytes(int KPAD, int CPAD) {
    return (64 * (KPAD + 2) + 56 * (CPAD + 8)) * 4;
}

extern "C" void kernel_launch(void* const* d_in, const int* in_sizes, int n_in,
                              void* d_out, int out_size) {
    const float* x     = (const float*)d_in[0];
    const int*   ei    = (const int*)d_in[1];
    const int*   batch = (const int*)d_in[2];
    const float* W1 = (const float*)d_in[3];
    const float* b1 = (const float*)d_in[4];
    const float* W2 = (const float*)d_in[5];
    const float* b2 = (const float*)d_in[6];
    const float* W3 = (const float*)d_in[7];
    const float* b3 = (const float*)d_in[8];
    const float* Wf1 = (const float*)d_in[9];
    const float* bf1 = (const float*)d_in[10];
    const float* Wf2 = (const float*)d_in[11];
    const float* bf2 = (const float*)d_in[12];
    float* out = (float*)d_out;

    float *xp, *agg, *h1, *h2, *h3, *Wp1, *bp1, *Wp2, *bp2, *Wp3, *bp3;
    cudaGetSymbolAddress((void**)&xp, g_xp);
    cudaGetSymbolAddress((void**)&agg, g_agg);
    cudaGetSymbolAddress((void**)&h1, g_h1);
    cudaGetSymbolAddress((void**)&h2, g_h2);
    cudaGetSymbolAddress((void**)&h3, g_h3);
    cudaGetSymbolAddress((void**)&Wp1, g_Wp1);
    cudaGetSymbolAddress((void**)&bp1, g_bp1);
    cudaGetSymbolAddress((void**)&Wp2, g_Wp2);
    cudaGetSymbolAddress((void**)&bp2, g_bp2);
    cudaGetSymbolAddress((void**)&Wp3, g_Wp3);
    cudaGetSymbolAddress((void**)&bp3, g_bp3);

    cudaFuncSetAttribute(k_gemm_mma<56, 64>,
                         cudaFuncAttributeMaxDynamicSharedMemorySize, smem_bytes(56, 64));
    cudaFuncSetAttribute(k_gemm_mma<56, 128>,
                         cudaFuncAttributeMaxDynamicSharedMemorySize, smem_bytes(56, 128));
    cudaFuncSetAttribute(k_gemm_mma<112, 224>,
                         cudaFuncAttributeMaxDynamicSharedMemorySize, smem_bytes(112, 224));

    k_setup<<<(S5 + 255) / 256, 256>>>(x, W1, b1, W2, b2, W3, b3);
    k_count<<<(NE + 255) / 256, 256>>>(ei);
    k_scan<<<1, 1024>>>();
    k_ghist<<<(NN + 255) / 256, 256>>>(batch);
    k_fill<<<(NT_EDGE + 255) / 256, 256>>>(ei);
    k_gscan<<<1, NG>>>();

    int ablk = (NN * 32 + 255) / 256;
    int gblk = (NN + 63) / 64;
    // layer 1: aggregate xp (56-wide), GEMM 56 -> 64(pad of 54) + relu
    k_agg56<56><<<ablk, 256>>>(xp, agg);
    k_gemm_mma<56, 64><<<gblk, 256, smem_bytes(56, 64)>>>(agg, Wp1, bp1, h1);
    // layer 2: aggregate h1 (stride 64, 56 useful incl. zero pad), GEMM 56 -> 128
    k_agg56<64><<<ablk, 256>>>(h1, agg);
    k_gemm_mma<56, 128><<<gblk, 256, smem_bytes(56, 128)>>>(agg, Wp2, bp2, h2);
    // layer 3: aggregate h2 (stride 128, 112 useful incl. zero pad), GEMM 112 -> 224
    k_agg112<<<ablk, 256>>>(h2, agg);
    k_gemm_mma<112, 224><<<gblk, 256, smem_bytes(112, 224)>>>(agg, Wp3, bp3, h3);

    k_pool<<<NG, 224>>>();
    k_mlp1<<<NG, 256>>>(Wf1, bf1);
    k_mlp2<<<NG, 128>>>(Wf2, bf2, out);
}

// round 7
// speedup vs baseline: 1.6539x; 1.1077x over previous
#include <cuda_runtime.h>
#include <cuda_bf16.h>

#define NN 100000
#define NE 1600000
#define NT_EDGE 1700000   // edges + self loops
#define NG 256

// ---------------- scratch (static device allocations; no runtime alloc) ----
__device__ int   g_cnt[NN];
__device__ int   g_fill[NN];
__device__ int   g_rowptr[NN + 1];
__device__ __align__(16) int2  g_edata[NT_EDGE];        // {src, f2i(norm)} by dst
__device__ __align__(16) __nv_bfloat16 g_xpb[NN * 56];  // x padded, bf16, stride 56
__device__ __align__(16) __nv_bfloat16 g_h1b[NN * 56];  // layer1 out bf16 (54 real)
__device__ __align__(16) __nv_bfloat16 g_h2b[NN * 112]; // layer2 out bf16 (108 real)
__device__ __align__(16) float g_agg[NN * 112];         // aggregation out fp32
__device__ __align__(16) float g_h3[NN * 224];          // layer3 out fp32 (216 real)
__device__ __align__(16) float g_Wp1[56 * 64];
__device__ __align__(16) float g_Wp2[56 * 128];
__device__ __align__(16) float g_Wp3[112 * 224];
__device__ float g_bp1[64], g_bp2[128], g_bp3[224];
__device__ float g_pool[NG * 216];
__device__ int   g_goff[NG + 1];
__device__ float g_g1[NG * 1024];

// ---------------- fused setup: init + padW x3 + x padding(bf16) ----------
#define PW1 (56 * 64 + 64)
#define PW2 (56 * 128 + 128)
#define PW3 (112 * 224 + 224)
#define S0 NN
#define S1 (S0 + PW1)
#define S2 (S1 + PW2)
#define S3 (S2 + PW3)
#define S4 (S3 + NN * 56)

__device__ __forceinline__ void padw_one(int j, const float* W, const float* b,
                                         float* Wp, float* bp, int K, int C,
                                         int KPAD, int CPAD) {
    int tot = KPAD * CPAD;
    if (j < tot) {
        int cc = j % CPAD, kk = j / CPAD;
        Wp[j] = (cc < C && kk < K) ? W[kk * C + cc] : 0.f;
    } else {
        int cc = j - tot;
        bp[cc] = (cc < C) ? b[cc] : 0.f;
    }
}

__global__ void k_setup(const float* __restrict__ x,
                        const float* __restrict__ W1, const float* __restrict__ b1,
                        const float* __restrict__ W2, const float* __restrict__ b2,
                        const float* __restrict__ W3, const float* __restrict__ b3) {
    int i = blockIdx.x * blockDim.x + threadIdx.x;
    if (i < S0) {
        g_cnt[i] = 1;              // self loop
        g_fill[i] = 0;
    } else if (i < S1) {
        padw_one(i - S0, W1, b1, g_Wp1, g_bp1, 54, 54, 56, 64);
    } else if (i < S2) {
        padw_one(i - S1, W2, b2, g_Wp2, g_bp2, 54, 108, 56, 128);
    } else if (i < S3) {
        padw_one(i - S2, W3, b3, g_Wp3, g_bp3, 108, 216, 112, 224);
    } else if (i < S4) {
        int j = i - S3;
        int r = j / 56, c = j - r * 56;
        g_xpb[j] = __float2bfloat16((c < 54) ? x[r * 54 + c] : 0.f);
    }
}

// ---------------- fused: degree count + sorted-batch boundary detect ------
__global__ void k_pre(const int* __restrict__ ei, const int* __restrict__ batch) {
    int i = blockIdx.x * blockDim.x + threadIdx.x;
    if (i < NE) {
        atomicAdd(&g_cnt[ei[NE + i]], 1);
    } else if (i < NE + NN) {
        int j = i - NE;
        int bi = batch[j];
        int bprev = (j > 0) ? batch[j - 1] : -1;
        for (int g = bprev + 1; g <= bi; g++) g_goff[g] = j;   // usually 0/1 iters
        if (j == NN - 1)
            for (int g = bi + 1; g <= NG; g++) g_goff[g] = NN;
    }
}

// single-block exclusive scan of g_cnt -> g_rowptr
__global__ void k_scan() {
    __shared__ int part[1024];
    const int CH = (NN + 1023) / 1024;
    int t = threadIdx.x;
    int lo = t * CH;
    int hi = min(lo + CH, NN);
    int s = 0;
    for (int i = lo; i < hi; i++) s += g_cnt[i];
    part[t] = s;
    __syncthreads();
    for (int off = 1; off < 1024; off <<= 1) {
        int v = (t >= off) ? part[t - off] : 0;
        __syncthreads();
        part[t] += v;
        __syncthreads();
    }
    int base = (t == 0) ? 0 : part[t - 1];
    for (int i = lo; i < hi; i++) { int c = g_cnt[i]; g_rowptr[i] = base; base += c; }
    if (t == 1023) g_rowptr[NN] = base;
}

__global__ void k_fill(const int* __restrict__ ei) {
    int i = blockIdx.x * blockDim.x + threadIdx.x;
    if (i >= NT_EDGE) return;
    int r, c;
    if (i < NE) { r = ei[i]; c = ei[NE + i]; }
    else        { r = c = i - NE; }
    float nrm = rsqrtf((float)g_cnt[r] * (float)g_cnt[c]);
    int pos = g_rowptr[c] + atomicAdd(&g_fill[c], 1);
    g_edata[pos] = make_int2(r, __float_as_int(nrm));
}

// ---------------- aggregation (bf16 gather, fp32 accumulate) --------------
__device__ __forceinline__ void acc8(float acc[8], float nrm, uint4 t) {
    float2 f0 = __bfloat1622float2(*(__nv_bfloat162*)&t.x);
    float2 f1 = __bfloat1622float2(*(__nv_bfloat162*)&t.y);
    float2 f2 = __bfloat1622float2(*(__nv_bfloat162*)&t.z);
    float2 f3 = __bfloat1622float2(*(__nv_bfloat162*)&t.w);
    acc[0] += nrm * f0.x; acc[1] += nrm * f0.y;
    acc[2] += nrm * f1.x; acc[3] += nrm * f1.y;
    acc[4] += nrm * f2.x; acc[5] += nrm * f2.y;
    acc[6] += nrm * f3.x; acc[7] += nrm * f3.y;
}

// 56-bf16 rows (112B = 7 uint4). 4 edges per warp (lane groups of 8, 7 active).
__global__ void k_agg56b(const __nv_bfloat16* __restrict__ in, float* __restrict__ out) {
    int w = (blockIdx.x * blockDim.x + threadIdx.x) >> 5;
    int lane = threadIdx.x & 31;
    if (w >= NN) return;
    int q = lane >> 3, sl = lane & 7;
    bool act = sl < 7;
    int e0 = g_rowptr[w], e1 = g_rowptr[w + 1];
    float acc[8];
#pragma unroll
    for (int j = 0; j < 8; j++) acc[j] = 0.f;
    for (int e = e0; e < e1; e += 4) {
        int idx = e + q;
        bool v = idx < e1;
        int2 ed = __ldg(&g_edata[v ? idx : e]);
        float nrm = v ? __int_as_float(ed.y) : 0.f;
        if (act) {
            const uint4* src = (const uint4*)(in + (long)ed.x * 56);
            acc8(acc, nrm, __ldg(&src[sl]));
        }
    }
#pragma unroll
    for (int j = 0; j < 8; j++) {
        acc[j] += __shfl_xor_sync(0xffffffffu, acc[j], 8);
        acc[j] += __shfl_xor_sync(0xffffffffu, acc[j], 16);
    }
    if (q == 0 && act) {
        float4* o = (float4*)(out + (long)w * 56 + sl * 8);
        o[0] = make_float4(acc[0], acc[1], acc[2], acc[3]);
        o[1] = make_float4(acc[4], acc[5], acc[6], acc[7]);
    }
}

// 112-bf16 rows (224B = 14 uint4). 2 edges per warp (half-warps, 14 active).
__global__ void k_agg112b(const __nv_bfloat16* __restrict__ in, float* __restrict__ out) {
    int w = (blockIdx.x * blockDim.x + threadIdx.x) >> 5;
    int lane = threadIdx.x & 31;
    if (w >= NN) return;
    int half = lane >> 4, sl = lane & 15;
    bool act = sl < 14;
    int e0 = g_rowptr[w], e1 = g_rowptr[w + 1];
    float acc[8];
#pragma unroll
    for (int j = 0; j < 8; j++) acc[j] = 0.f;
    for (int e = e0; e < e1; e += 2) {
        int idx = e + half;
        bool v = idx < e1;
        int2 ed = __ldg(&g_edata[v ? idx : e]);
        float nrm = v ? __int_as_float(ed.y) : 0.f;
        if (act) {
            const uint4* src = (const uint4*)(in + (long)ed.x * 112);
            acc8(acc, nrm, __ldg(&src[sl]));
        }
    }
#pragma unroll
    for (int j = 0; j < 8; j++)
        acc[j] += __shfl_xor_sync(0xffffffffu, acc[j], 16);
    if (half == 0 && act) {
        float4* o = (float4*)(out + (long)w * 112 + sl * 8);
        o[0] = make_float4(acc[0], acc[1], acc[2], acc[3]);
        o[1] = make_float4(acc[4], acc[5], acc[6], acc[7]);
    }
}

// ---------------- tf32 tensor-core GEMM ----------------
__device__ __forceinline__ unsigned f2tf(float v) {
    unsigned u;
    asm("cvt.rna.tf32.f32 %0, %1;" : "=r"(u) : "f"(v));
    return u;
}

__device__ __forceinline__ void mma_tf32(float c[4], const unsigned a[4], const unsigned b[2]) {
    asm volatile(
        "mma.sync.aligned.m16n8k8.row.col.f32.tf32.tf32.f32 "
        "{%0,%1,%2,%3}, {%4,%5,%6,%7}, {%8,%9}, {%0,%1,%2,%3};\n"
        : "+f"(c[0]), "+f"(c[1]), "+f"(c[2]), "+f"(c[3])
        : "r"(a[0]), "r"(a[1]), "r"(a[2]), "r"(a[3]), "r"(b[0]), "r"(b[1]));
}

// BF16OUT: write bf16 rows of stride SOUT (only cols < SOUT); else fp32 stride CPAD.
template <int KPAD, int CPAD, bool BF16OUT, int SOUT>
__global__ __launch_bounds__(256)
void k_gemm_mma(const float* __restrict__ A, const float* __restrict__ W,
                const float* __restrict__ bias, void* __restrict__ outv) {
    extern __shared__ float sm[];
    constexpr int ASTR = KPAD + 2;
    constexpr int WSTR = CPAD + 8;
    constexpr int KCH = 56;
    constexpr int NTILES = CPAD / 32;
    float* As = sm;                       // [64][ASTR]
    float* Ws = sm + 64 * ASTR;           // [KCH][WSTR]

    int tid = threadIdx.x;
    int w = tid >> 5, lane = tid & 31;
    int g = lane >> 2, ctg = lane & 3;
    int wm = w & 1, wn = w >> 1;
    int row0 = blockIdx.x * 64;

    float c[2][NTILES][4];
#pragma unroll
    for (int mt = 0; mt < 2; mt++)
#pragma unroll
        for (int nt = 0; nt < NTILES; nt++)
#pragma unroll
            for (int i = 0; i < 4; i++) c[mt][nt][i] = 0.f;

    for (int i = tid * 4; i < 64 * KPAD; i += 256 * 4) {
        int r = i / KPAD, k = i % KPAD;
        float4 v = make_float4(0.f, 0.f, 0.f, 0.f);
        if (row0 + r < NN) v = *(const float4*)&A[(long)(row0 + r) * KPAD + k];
        As[r * ASTR + k + 0] = __uint_as_float(f2tf(v.x));
        As[r * ASTR + k + 1] = __uint_as_float(f2tf(v.y));
        As[r * ASTR + k + 2] = __uint_as_float(f2tf(v.z));
        As[r * ASTR + k + 3] = __uint_as_float(f2tf(v.w));
    }

#pragma unroll 1
    for (int kc = 0; kc < KPAD; kc += KCH) {
        constexpr int kchunk = (KPAD < KCH) ? KPAD : KCH;
        for (int i = tid * 4; i < kchunk * CPAD; i += 256 * 4) {
            int kk = i / CPAD, cc = i % CPAD;
            float4 v = *(const float4*)&W[(long)(kc + kk) * CPAD + cc];
            float4 t;
            t.x = __uint_as_float(f2tf(v.x));
            t.y = __uint_as_float(f2tf(v.y));
            t.z = __uint_as_float(f2tf(v.z));
            t.w = __uint_as_float(f2tf(v.w));
            *(float4*)&Ws[kk * WSTR + cc] = t;
        }
        __syncthreads();

#pragma unroll
        for (int ks = 0; ks < kchunk; ks += 8) {
            unsigned a[2][4];
#pragma unroll
            for (int mt = 0; mt < 2; mt++) {
                int ar = wm * 32 + mt * 16;
                int kb = kc + ks + ctg;
                a[mt][0] = __float_as_uint(As[(ar + g) * ASTR + kb]);
                a[mt][1] = __float_as_uint(As[(ar + g + 8) * ASTR + kb]);
                a[mt][2] = __float_as_uint(As[(ar + g) * ASTR + kb + 4]);
                a[mt][3] = __float_as_uint(As[(ar + g + 8) * ASTR + kb + 4]);
            }
            unsigned b[NTILES][2];
#pragma unroll
            for (int nt = 0; nt < NTILES; nt++) {
                int col = wn * (CPAD / 4) + nt * 8 + g;
                b[nt][0] = __float_as_uint(Ws[(ks + ctg) * WSTR + col]);
                b[nt][1] = __float_as_uint(Ws[(ks + ctg + 4) * WSTR + col]);
            }
#pragma unroll
            for (int mt = 0; mt < 2; mt++)
#pragma unroll
                for (int nt = 0; nt < NTILES; nt++)
                    mma_tf32(c[mt][nt], a[mt], b[nt]);
        }
        __syncthreads();
    }

#pragma unroll
    for (int mt = 0; mt < 2; mt++) {
        int r0 = row0 + wm * 32 + mt * 16 + g;
#pragma unroll
        for (int nt = 0; nt < NTILES; nt++) {
            int col = wn * (CPAD / 4) + nt * 8 + 2 * ctg;
            float b0 = bias[col], b1 = bias[col + 1];
            float v0x = fmaxf(c[mt][nt][0] + b0, 0.f);
            float v0y = fmaxf(c[mt][nt][1] + b1, 0.f);
            float v1x = fmaxf(c[mt][nt][2] + b0, 0.f);
            float v1y = fmaxf(c[mt][nt][3] + b1, 0.f);
            if (BF16OUT) {
                __nv_bfloat16* outb = (__nv_bfloat16*)outv;
                if (col < SOUT) {
                    if (r0 < NN)
                        *(__nv_bfloat162*)&outb[(long)r0 * SOUT + col] =
                            __float22bfloat162_rn(make_float2(v0x, v0y));
                    if (r0 + 8 < NN)
                        *(__nv_bfloat162*)&outb[(long)(r0 + 8) * SOUT + col] =
                            __float22bfloat162_rn(make_float2(v1x, v1y));
                }
            } else {
                float* outf = (float*)outv;
                if (r0 < NN)
                    *(float2*)&outf[(long)r0 * CPAD + col] = make_float2(v0x, v0y);
                if (r0 + 8 < NN)
                    *(float2*)&outf[(long)(r0 + 8) * CPAD + col] = make_float2(v1x, v1y);
            }
        }
    }
}

// ---------------- pooling ----------------
__global__ void k_pool() {    // grid NG, block 224
    int g = blockIdx.x, f = threadIdx.x;
    if (f >= 216) return;
    int v0 = g_goff[g], v1 = g_goff[g + 1];
    float s = 0.f;
    for (int v = v0; v < v1; v++) s += g_h3[(long)v * 224 + f];
    float cnt = (float)(v1 - v0);
    g_pool[g * 216 + f] = s / fmaxf(cnt, 1.f);
}

// ---------------- MLP (fp32) ----------------
__global__ void k_mlp1(const float* __restrict__ Wf1, const float* __restrict__ bf1) {
    __shared__ float ps[216];
    int g = blockIdx.x, t = threadIdx.x;       // 256 threads
    if (t < 216) ps[t] = g_pool[g * 216 + t];
    __syncthreads();
    float acc[4] = {0.f, 0.f, 0.f, 0.f};
    for (int k = 0; k < 216; k++) {
        float a = ps[k];
#pragma unroll
        for (int j = 0; j < 4; j++) acc[j] += a * Wf1[k * 1024 + t + 256 * j];
    }
#pragma unroll
    for (int j = 0; j < 4; j++) {
        int c = t + 256 * j;
        g_g1[g * 1024 + c] = fmaxf(acc[j] + bf1[c], 0.f);
    }
}

__global__ void k_mlp2(const float* __restrict__ Wf2, const float* __restrict__ bf2,
                       float* __restrict__ out) {
    __shared__ float ps[1024];
    int g = blockIdx.x, t = threadIdx.x;       // 128 threads
    for (int i = t; i < 1024; i += 128) ps[i] = g_g1[g * 1024 + i];
    __syncthreads();
    float acc = 0.f;
    for (int k = 0; k < 1024; k++) acc += ps[k] * Wf2[k * 128 + t];
    out[g * 128 + t] = acc + bf2[t];
}

// ---------------- launch ----------------
static int smem_bytes(int KPAD, int CPAD) {
    return (64 * (KPAD + 2) + 56 * (CPAD + 8)) * 4;
}

extern "C" void kernel_launch(void* const* d_in, const int* in_sizes, int n_in,
                              void* d_out, int out_size) {
    const float* x     = (const float*)d_in[0];
    const int*   ei    = (const int*)d_in[1];
    const int*   batch = (const int*)d_in[2];
    const float* W1 = (const float*)d_in[3];
    const float* b1 = (const float*)d_in[4];
    const float* W2 = (const float*)d_in[5];
    const float* b2 = (const float*)d_in[6];
    const float* W3 = (const float*)d_in[7];
    const float* b3 = (const float*)d_in[8];
    const float* Wf1 = (const float*)d_in[9];
    const float* bf1 = (const float*)d_in[10];
    const float* Wf2 = (const float*)d_in[11];
    const float* bf2 = (const float*)d_in[12];
    float* out = (float*)d_out;

    float *agg, *h3, *Wp1, *bp1, *Wp2, *bp2, *Wp3, *bp3;
    __nv_bfloat16 *xpb, *h1b, *h2b;
    cudaGetSymbolAddress((void**)&xpb, g_xpb);
    cudaGetSymbolAddress((void**)&h1b, g_h1b);
    cudaGetSymbolAddress((void**)&h2b, g_h2b);
    cudaGetSymbolAddress((void**)&agg, g_agg);
    cudaGetSymbolAddress((void**)&h3, g_h3);
    cudaGetSymbolAddress((void**)&Wp1, g_Wp1);
    cudaGetSymbolAddress((void**)&bp1, g_bp1);
    cudaGetSymbolAddress((void**)&Wp2, g_Wp2);
    cudaGetSymbolAddress((void**)&bp2, g_bp2);
    cudaGetSymbolAddress((void**)&Wp3, g_Wp3);
    cudaGetSymbolAddress((void**)&bp3, g_bp3);

    cudaFuncSetAttribute(k_gemm_mma<56, 64, true, 56>,
                         cudaFuncAttributeMaxDynamicSharedMemorySize, smem_bytes(56, 64));
    cudaFuncSetAttribute(k_gemm_mma<56, 128, true, 112>,
                         cudaFuncAttributeMaxDynamicSharedMemorySize, smem_bytes(56, 128));
    cudaFuncSetAttribute(k_gemm_mma<112, 224, false, 224>,
                         cudaFuncAttributeMaxDynamicSharedMemorySize, smem_bytes(112, 224));

    k_setup<<<(S4 + 255) / 256, 256>>>(x, W1, b1, W2, b2, W3, b3);
    k_pre<<<(NE + NN + 255) / 256, 256>>>(ei, batch);
    k_scan<<<1, 1024>>>();
    k_fill<<<(NT_EDGE + 255) / 256, 256>>>(ei);

    int ablk = (NN * 32 + 255) / 256;
    int gblk = (NN + 63) / 64;
    // layer 1: aggregate xpb (bf16, 56), GEMM 56 -> 64 + relu -> h1b (bf16, 56)
    k_agg56b<<<ablk, 256>>>(xpb, agg);
    k_gemm_mma<56, 64, true, 56><<<gblk, 256, smem_bytes(56, 64)>>>(agg, Wp1, bp1, h1b);
    // layer 2: aggregate h1b, GEMM 56 -> 128 + relu -> h2b (bf16, 112)
    k_agg56b<<<ablk, 256>>>(h1b, agg);
    k_gemm_mma<56, 128, true, 112><<<gblk, 256, smem_bytes(56, 128)>>>(agg, Wp2, bp2, h2b);
    // layer 3: aggregate h2b (112), GEMM 112 -> 224 + relu -> h3 (fp32)
    k_agg112b<<<ablk, 256>>>(h2b, agg);
    k_gemm_mma<112, 224, false, 224><<<gblk, 256, smem_bytes(112, 224)>>>(agg, Wp3, bp3, h3);

    k_pool<<<NG, 224>>>();
    k_mlp1<<<NG, 256>>>(Wf1, bf1);
    k_mlp2<<<NG, 128>>>(Wf2, bf2, out);
}

// round 8
// speedup vs baseline: 2.2300x; 1.3483x over previous
#include <cuda_runtime.h>
#include <cuda_bf16.h>

#define NN 100000
#define NE 1600000
#define NT_EDGE 1700000   // edges + self loops
#define NG 256
#define NBLK 391          // ceil(NN/256)

// ---------------- scratch (static device allocations; no runtime alloc) ----
__device__ int   g_cnt[NN];
__device__ int   g_fill[NN];
__device__ int   g_rowptr[NN + 1];
__device__ int   g_bsum[NBLK];
__device__ __align__(16) int2  g_edata[NT_EDGE];        // {src, f2i(norm)} by dst
__device__ __align__(256) __nv_bfloat16 g_xpb[NN * 64];  // x padded, bf16, stride 64 (1 line)
__device__ __align__(256) __nv_bfloat16 g_h1b[NN * 64];  // layer1 out bf16 (54 real)
__device__ __align__(256) __nv_bfloat16 g_h2b[NN * 128]; // layer2 out bf16 (108 real)
__device__ __align__(256) __nv_bfloat16 g_h3b[NN * 224]; // layer3 out bf16 (216 real)
__device__ __align__(16) float g_agg[NN * 112];          // aggregation out fp32
__device__ __align__(16) float g_Wp1[56 * 64];
__device__ __align__(16) float g_Wp2[56 * 128];
__device__ __align__(16) float g_Wp3[112 * 224];
__device__ float g_bp1[64], g_bp2[128], g_bp3[224];
__device__ float g_pool[NG * 216];
__device__ int   g_goff[NG + 1];
__device__ float g_g1[NG * 1024];

// ---------------- fused setup: init + padW x3 + x padding(bf16) ----------
#define PW1 (56 * 64 + 64)
#define PW2 (56 * 128 + 128)
#define PW3 (112 * 224 + 224)
#define S0 NN
#define S1 (S0 + PW1)
#define S2 (S1 + PW2)
#define S3 (S2 + PW3)
#define S4 (S3 + NN * 64)

__device__ __forceinline__ void padw_one(int j, const float* W, const float* b,
                                         float* Wp, float* bp, int K, int C,
                                         int KPAD, int CPAD) {
    int tot = KPAD * CPAD;
    if (j < tot) {
        int cc = j % CPAD, kk = j / CPAD;
        Wp[j] = (cc < C && kk < K) ? W[kk * C + cc] : 0.f;
    } else {
        int cc = j - tot;
        bp[cc] = (cc < C) ? b[cc] : 0.f;
    }
}

__global__ void k_setup(const float* __restrict__ x,
                        const float* __restrict__ W1, const float* __restrict__ b1,
                        const float* __restrict__ W2, const float* __restrict__ b2,
                        const float* __restrict__ W3, const float* __restrict__ b3) {
    int i = blockIdx.x * blockDim.x + threadIdx.x;
    if (i < S0) {
        g_cnt[i] = 1;              // self loop
        g_fill[i] = 0;
    } else if (i < S1) {
        padw_one(i - S0, W1, b1, g_Wp1, g_bp1, 54, 54, 56, 64);
    } else if (i < S2) {
        padw_one(i - S1, W2, b2, g_Wp2, g_bp2, 54, 108, 56, 128);
    } else if (i < S3) {
        padw_one(i - S2, W3, b3, g_Wp3, g_bp3, 108, 216, 112, 224);
    } else if (i < S4) {
        int j = i - S3;
        int r = j >> 6, c = j & 63;
        g_xpb[j] = __float2bfloat16((c < 54) ? x[r * 54 + c] : 0.f);
    }
}

// ---------------- fused: degree count + sorted-batch boundary detect ------
__global__ void k_pre(const int* __restrict__ ei, const int* __restrict__ batch) {
    int i = blockIdx.x * blockDim.x + threadIdx.x;
    if (i < NE) {
        atomicAdd(&g_cnt[ei[NE + i]], 1);
    } else if (i < NE + NN) {
        int j = i - NE;
        int bi = batch[j];
        int bprev = (j > 0) ? batch[j - 1] : -1;
        for (int g = bprev + 1; g <= bi; g++) g_goff[g] = j;
        if (j == NN - 1)
            for (int g = bi + 1; g <= NG; g++) g_goff[g] = NN;
    }
}

// ---------------- parallel scan: block sums -> scan sums -> local scan ----
__global__ void k_s1() {            // grid NBLK, block 256
    int b = blockIdx.x, t = threadIdx.x;
    int i = b * 256 + t;
    int v = (i < NN) ? g_cnt[i] : 0;
#pragma unroll
    for (int off = 16; off > 0; off >>= 1)
        v += __shfl_down_sync(0xffffffffu, v, off);
    __shared__ int sm[8];
    if ((t & 31) == 0) sm[t >> 5] = v;
    __syncthreads();
    if (t == 0) {
        int s = 0;
#pragma unroll
        for (int j = 0; j < 8; j++) s += sm[j];
        g_bsum[b] = s;
    }
}

__global__ void k_s2() {            // 1 block, 512 threads: exclusive scan of g_bsum
    __shared__ int p[512];
    int t = threadIdx.x;
    int v = (t < NBLK) ? g_bsum[t] : 0;
    p[t] = v;
    __syncthreads();
    for (int off = 1; off < 512; off <<= 1) {
        int u = (t >= off) ? p[t - off] : 0;
        __syncthreads();
        p[t] += u;
        __syncthreads();
    }
    if (t < NBLK) g_bsum[t] = p[t] - v;   // exclusive
}

__global__ void k_s3() {            // grid NBLK, block 256: local scan + offset
    __shared__ int p[256];
    int b = blockIdx.x, t = threadIdx.x;
    int i = b * 256 + t;
    int v = (i < NN) ? g_cnt[i] : 0;
    p[t] = v;
    __syncthreads();
    for (int off = 1; off < 256; off <<= 1) {
        int u = (t >= off) ? p[t - off] : 0;
        __syncthreads();
        p[t] += u;
        __syncthreads();
    }
    int excl = p[t] - v + g_bsum[b];
    if (i < NN) g_rowptr[i] = excl;
    if (i == NN - 1) g_rowptr[NN] = excl + v;
}

__global__ void k_fill(const int* __restrict__ ei) {
    int i = blockIdx.x * blockDim.x + threadIdx.x;
    if (i >= NT_EDGE) return;
    int r, c;
    if (i < NE) { r = ei[i]; c = ei[NE + i]; }
    else        { r = c = i - NE; }
    float nrm = rsqrtf((float)g_cnt[r] * (float)g_cnt[c]);
    int pos = g_rowptr[c] + atomicAdd(&g_fill[c], 1);
    g_edata[pos] = make_int2(r, __float_as_int(nrm));
}

// ---------------- aggregation (bf16 gather, fp32 accumulate) --------------
__device__ __forceinline__ void acc8(float acc[8], float nrm, uint4 t) {
    float2 f0 = __bfloat1622float2(*(__nv_bfloat162*)&t.x);
    float2 f1 = __bfloat1622float2(*(__nv_bfloat162*)&t.y);
    float2 f2 = __bfloat1622float2(*(__nv_bfloat162*)&t.z);
    float2 f3 = __bfloat1622float2(*(__nv_bfloat162*)&t.w);
    acc[0] += nrm * f0.x; acc[1] += nrm * f0.y;
    acc[2] += nrm * f1.x; acc[3] += nrm * f1.y;
    acc[4] += nrm * f2.x; acc[5] += nrm * f2.y;
    acc[6] += nrm * f3.x; acc[7] += nrm * f3.y;
}

// 64-bf16 rows (128B = exactly 1 cache line). 4 edges/warp, all 32 lanes active.
// Writes first 56 fp32 (row pad cols are zero).
__global__ void k_agg64b(const __nv_bfloat16* __restrict__ in, float* __restrict__ out) {
    int w = (blockIdx.x * blockDim.x + threadIdx.x) >> 5;
    int lane = threadIdx.x & 31;
    if (w >= NN) return;
    int q = lane >> 3, sl = lane & 7;
    int e0 = g_rowptr[w], e1 = g_rowptr[w + 1];
    float acc[8];
#pragma unroll
    for (int j = 0; j < 8; j++) acc[j] = 0.f;
    for (int e = e0; e < e1; e += 4) {
        int idx = e + q;
        bool v = idx < e1;
        int2 ed = __ldg(&g_edata[v ? idx : e]);
        float nrm = v ? __int_as_float(ed.y) : 0.f;
        const uint4* src = (const uint4*)(in + (long)ed.x * 64);
        acc8(acc, nrm, __ldg(&src[sl]));
    }
#pragma unroll
    for (int j = 0; j < 8; j++) {
        acc[j] += __shfl_xor_sync(0xffffffffu, acc[j], 8);
        acc[j] += __shfl_xor_sync(0xffffffffu, acc[j], 16);
    }
    if (q == 0 && sl < 7) {
        float4* o = (float4*)(out + (long)w * 56 + sl * 8);
        o[0] = make_float4(acc[0], acc[1], acc[2], acc[3]);
        o[1] = make_float4(acc[4], acc[5], acc[6], acc[7]);
    }
}

// 128-bf16 rows (256B = 2 lines). 2 edges/warp, all 32 lanes active.
// Writes first 112 fp32.
__global__ void k_agg128b(const __nv_bfloat16* __restrict__ in, float* __restrict__ out) {
    int w = (blockIdx.x * blockDim.x + threadIdx.x) >> 5;
    int lane = threadIdx.x & 31;
    if (w >= NN) return;
    int half = lane >> 4, sl = lane & 15;
    int e0 = g_rowptr[w], e1 = g_rowptr[w + 1];
    float acc[8];
#pragma unroll
    for (int j = 0; j < 8; j++) acc[j] = 0.f;
    for (int e = e0; e < e1; e += 2) {
        int idx = e + half;
        bool v = idx < e1;
        int2 ed = __ldg(&g_edata[v ? idx : e]);
        float nrm = v ? __int_as_float(ed.y) : 0.f;
        const uint4* src = (const uint4*)(in + (long)ed.x * 128);
        acc8(acc, nrm, __ldg(&src[sl]));
    }
#pragma unroll
    for (int j = 0; j < 8; j++)
        acc[j] += __shfl_xor_sync(0xffffffffu, acc[j], 16);
    if (half == 0 && sl < 14) {
        float4* o = (float4*)(out + (long)w * 112 + sl * 8);
        o[0] = make_float4(acc[0], acc[1], acc[2], acc[3]);
        o[1] = make_float4(acc[4], acc[5], acc[6], acc[7]);
    }
}

// ---------------- tf32 tensor-core GEMM, bf16 output ----------------
__device__ __forceinline__ unsigned f2tf(float v) {
    unsigned u;
    asm("cvt.rna.tf32.f32 %0, %1;" : "=r"(u) : "f"(v));
    return u;
}

__device__ __forceinline__ void mma_tf32(float c[4], const unsigned a[4], const unsigned b[2]) {
    asm volatile(
        "mma.sync.aligned.m16n8k8.row.col.f32.tf32.tf32.f32 "
        "{%0,%1,%2,%3}, {%4,%5,%6,%7}, {%8,%9}, {%0,%1,%2,%3};\n"
        : "+f"(c[0]), "+f"(c[1]), "+f"(c[2]), "+f"(c[3])
        : "r"(a[0]), "r"(a[1]), "r"(a[2]), "r"(a[3]), "r"(b[0]), "r"(b[1]));
}

template <int KPAD, int CPAD>
__global__ __launch_bounds__(256)
void k_gemm_mma(const float* __restrict__ A, const float* __restrict__ W,
                const float* __restrict__ bias, __nv_bfloat16* __restrict__ out) {
    extern __shared__ float sm[];
    constexpr int ASTR = KPAD + 2;
    constexpr int WSTR = CPAD + 8;
    constexpr int KCH = 56;
    constexpr int NTILES = CPAD / 32;
    float* As = sm;                       // [64][ASTR]
    float* Ws = sm + 64 * ASTR;           // [KCH][WSTR]

    int tid = threadIdx.x;
    int w = tid >> 5, lane = tid & 31;
    int g = lane >> 2, ctg = lane & 3;
    int wm = w & 1, wn = w >> 1;
    int row0 = blockIdx.x * 64;

    float c[2][NTILES][4];
#pragma unroll
    for (int mt = 0; mt < 2; mt++)
#pragma unroll
        for (int nt = 0; nt < NTILES; nt++)
#pragma unroll
            for (int i = 0; i < 4; i++) c[mt][nt][i] = 0.f;

    for (int i = tid * 4; i < 64 * KPAD; i += 256 * 4) {
        int r = i / KPAD, k = i % KPAD;
        float4 v = make_float4(0.f, 0.f, 0.f, 0.f);
        if (row0 + r < NN) v = *(const float4*)&A[(long)(row0 + r) * KPAD + k];
        As[r * ASTR + k + 0] = __uint_as_float(f2tf(v.x));
        As[r * ASTR + k + 1] = __uint_as_float(f2tf(v.y));
        As[r * ASTR + k + 2] = __uint_as_float(f2tf(v.z));
        As[r * ASTR + k + 3] = __uint_as_float(f2tf(v.w));
    }

#pragma unroll 1
    for (int kc = 0; kc < KPAD; kc += KCH) {
        constexpr int kchunk = (KPAD < KCH) ? KPAD : KCH;
        for (int i = tid * 4; i < kchunk * CPAD; i += 256 * 4) {
            int kk = i / CPAD, cc = i % CPAD;
            float4 v = *(const float4*)&W[(long)(kc + kk) * CPAD + cc];
            float4 t;
            t.x = __uint_as_float(f2tf(v.x));
            t.y = __uint_as_float(f2tf(v.y));
            t.z = __uint_as_float(f2tf(v.z));
            t.w = __uint_as_float(f2tf(v.w));
            *(float4*)&Ws[kk * WSTR + cc] = t;
        }
        __syncthreads();

#pragma unroll
        for (int ks = 0; ks < kchunk; ks += 8) {
            unsigned a[2][4];
#pragma unroll
            for (int mt = 0; mt < 2; mt++) {
                int ar = wm * 32 + mt * 16;
                int kb = kc + ks + ctg;
                a[mt][0] = __float_as_uint(As[(ar + g) * ASTR + kb]);
                a[mt][1] = __float_as_uint(As[(ar + g + 8) * ASTR + kb]);
                a[mt][2] = __float_as_uint(As[(ar + g) * ASTR + kb + 4]);
                a[mt][3] = __float_as_uint(As[(ar + g + 8) * ASTR + kb + 4]);
            }
            unsigned b[NTILES][2];
#pragma unroll
            for (int nt = 0; nt < NTILES; nt++) {
                int col = wn * (CPAD / 4) + nt * 8 + g;
                b[nt][0] = __float_as_uint(Ws[(ks + ctg) * WSTR + col]);
                b[nt][1] = __float_as_uint(Ws[(ks + ctg + 4) * WSTR + col]);
            }
#pragma unroll
            for (int mt = 0; mt < 2; mt++)
#pragma unroll
                for (int nt = 0; nt < NTILES; nt++)
                    mma_tf32(c[mt][nt], a[mt], b[nt]);
        }
        __syncthreads();
    }

#pragma unroll
    for (int mt = 0; mt < 2; mt++) {
        int r0 = row0 + wm * 32 + mt * 16 + g;
#pragma unroll
        for (int nt = 0; nt < NTILES; nt++) {
            int col = wn * (CPAD / 4) + nt * 8 + 2 * ctg;
            float b0 = bias[col], b1 = bias[col + 1];
            if (r0 < NN)
                *(__nv_bfloat162*)&out[(long)r0 * CPAD + col] =
                    __float22bfloat162_rn(make_float2(
                        fmaxf(c[mt][nt][0] + b0, 0.f), fmaxf(c[mt][nt][1] + b1, 0.f)));
            if (r0 + 8 < NN)
                *(__nv_bfloat162*)&out[(long)(r0 + 8) * CPAD + col] =
                    __float22bfloat162_rn(make_float2(
                        fmaxf(c[mt][nt][2] + b0, 0.f), fmaxf(c[mt][nt][3] + b1, 0.f)));
        }
    }
}

// ---------------- pooling (bf16 in, fp32 accumulate) ----------------
__global__ void k_pool() {    // grid NG, block 224
    int g = blockIdx.x, f = threadIdx.x;
    if (f >= 216) return;
    int v0 = g_goff[g], v1 = g_goff[g + 1];
    float s = 0.f;
    for (int v = v0; v < v1; v++) s += __bfloat162float(g_h3b[(long)v * 224 + f]);
    float cnt = (float)(v1 - v0);
    g_pool[g * 216 + f] = s / fmaxf(cnt, 1.f);
}

// ---------------- tiled MLP head (fp32) ----------------
// mlp1: [256, 216] @ [216, 1024] + bias, relu. grid 128 = 4 row-tiles x 32 col-tiles.
__global__ __launch_bounds__(256) void k_mlp1(const float* __restrict__ Wf1,
                                              const float* __restrict__ bf1) {
    extern __shared__ float smm[];
    float* Pt = smm;            // [64][216]
    float* Wt = smm + 64 * 216; // [216][32]
    int b = blockIdx.x, t = threadIdx.x;
    int bi = b >> 5, bj = b & 31;
    int g0 = bi * 64, c0 = bj * 32;
    for (int i = t; i < 64 * 216; i += 256) {
        int r = i / 216, k = i - r * 216;
        Pt[i] = g_pool[(g0 + r) * 216 + k];
    }
    for (int i = t; i < 216 * 32; i += 256) {
        int k = i >> 5, c = i & 31;
        Wt[i] = Wf1[k * 1024 + c0 + c];
    }
    __syncthreads();
    int c = t & 31, rb = t >> 5;
    float acc[8];
#pragma unroll
    for (int j = 0; j < 8; j++) acc[j] = 0.f;
    for (int k = 0; k < 216; k++) {
        float wv = Wt[k * 32 + c];
#pragma unroll
        for (int j = 0; j < 8; j++)
            acc[j] += Pt[(rb + 8 * j) * 216 + k] * wv;
    }
    float bias = bf1[c0 + c];
#pragma unroll
    for (int j = 0; j < 8; j++)
        g_g1[(g0 + rb + 8 * j) * 1024 + c0 + c] = fmaxf(acc[j] + bias, 0.f);
}

// mlp2: [256, 1024] @ [1024, 128] + bias. grid 16 = 4 row-tiles x 4 col-tiles.
__global__ __launch_bounds__(256) void k_mlp2(const float* __restrict__ Wf2,
                                              const float* __restrict__ bf2,
                                              float* __restrict__ out) {
    __shared__ float At[64 * 128];   // 32KB
    __shared__ float Wt[128 * 32];   // 16KB
    int b = blockIdx.x, t = threadIdx.x;
    int bi = b >> 2, bj = b & 3;
    int g0 = bi * 64, c0 = bj * 32;
    int c = t & 31, rb = t >> 5;
    float acc[8];
#pragma unroll
    for (int j = 0; j < 8; j++) acc[j] = 0.f;
    for (int k0 = 0; k0 < 1024; k0 += 128) {
        for (int i = t; i < 64 * 128; i += 256) {
            int r = i >> 7, k = i & 127;
            At[i] = g_g1[(g0 + r) * 1024 + k0 + k];
        }
        for (int i = t; i < 128 * 32; i += 256) {
            int k = i >> 5, cc = i & 31;
            Wt[i] = Wf2[(k0 + k) * 128 + c0 + cc];
        }
        __syncthreads();
        for (int k = 0; k < 128; k++) {
            float wv = Wt[k * 32 + c];
#pragma unroll
            for (int j = 0; j < 8; j++)
                acc[j] += At[(rb + 8 * j) * 128 + k] * wv;
        }
        __syncthreads();
    }
    float bias = bf2[c0 + c];
#pragma unroll
    for (int j = 0; j < 8; j++)
        out[(g0 + rb + 8 * j) * 128 + c0 + c] = acc[j] + bias;
}

// ---------------- launch ----------------
static int smem_bytes(int KPAD, int CPAD) {
    return (64 * (KPAD + 2) + 56 * (CPAD + 8)) * 4;
}

extern "C" void kernel_launch(void* const* d_in, const int* in_sizes, int n_in,
                              void* d_out, int out_size) {
    const float* x     = (const float*)d_in[0];
    const int*   ei    = (const int*)d_in[1];
    const int*   batch = (const int*)d_in[2];
    const float* W1 = (const float*)d_in[3];
    const float* b1 = (const float*)d_in[4];
    const float* W2 = (const float*)d_in[5];
    const float* b2 = (const float*)d_in[6];
    const float* W3 = (const float*)d_in[7];
    const float* b3 = (const float*)d_in[8];
    const float* Wf1 = (const float*)d_in[9];
    const float* bf1 = (const float*)d_in[10];
    const float* Wf2 = (const float*)d_in[11];
    const float* bf2 = (const float*)d_in[12];
    float* out = (float*)d_out;

    float *agg, *Wp1, *bp1, *Wp2, *bp2, *Wp3, *bp3;
    __nv_bfloat16 *xpb, *h1b, *h2b, *h3b;
    cudaGetSymbolAddress((void**)&xpb, g_xpb);
    cudaGetSymbolAddress((void**)&h1b, g_h1b);
    cudaGetSymbolAddress((void**)&h2b, g_h2b);
    cudaGetSymbolAddress((void**)&h3b, g_h3b);
    cudaGetSymbolAddress((void**)&agg, g_agg);
    cudaGetSymbolAddress((void**)&Wp1, g_Wp1);
    cudaGetSymbolAddress((void**)&bp1, g_bp1);
    cudaGetSymbolAddress((void**)&Wp2, g_Wp2);
    cudaGetSymbolAddress((void**)&bp2, g_bp2);
    cudaGetSymbolAddress((void**)&Wp3, g_Wp3);
    cudaGetSymbolAddress((void**)&bp3, g_bp3);

    cudaFuncSetAttribute(k_gemm_mma<56, 64>,
                         cudaFuncAttributeMaxDynamicSharedMemorySize, smem_bytes(56, 64));
    cudaFuncSetAttribute(k_gemm_mma<56, 128>,
                         cudaFuncAttributeMaxDynamicSharedMemorySize, smem_bytes(56, 128));
    cudaFuncSetAttribute(k_gemm_mma<112, 224>,
                         cudaFuncAttributeMaxDynamicSharedMemorySize, smem_bytes(112, 224));
    int mlp1_smem = (64 * 216 + 216 * 32) * 4;
    cudaFuncSetAttribute(k_mlp1, cudaFuncAttributeMaxDynamicSharedMemorySize, mlp1_smem);

    k_setup<<<(S4 + 255) / 256, 256>>>(x, W1, b1, W2, b2, W3, b3);
    k_pre<<<(NE + NN + 255) / 256, 256>>>(ei, batch);
    k_s1<<<NBLK, 256>>>();
    k_s2<<<1, 512>>>();
    k_s3<<<NBLK, 256>>>();
    k_fill<<<(NT_EDGE + 255) / 256, 256>>>(ei);

    int ablk = (NN * 32 + 255) / 256;
    int gblk = (NN + 63) / 64;
    // layer 1: aggregate xpb (bf16, 64), GEMM 56 -> 64 + relu -> h1b (bf16, 64)
    k_agg64b<<<ablk, 256>>>(xpb, agg);
    k_gemm_mma<56, 64><<<gblk, 256, smem_bytes(56, 64)>>>(agg, Wp1, bp1, h1b);
    // layer 2: aggregate h1b, GEMM 56 -> 128 + relu -> h2b (bf16, 128)
    k_agg64b<<<ablk, 256>>>(h1b, agg);
    k_gemm_mma<56, 128><<<gblk, 256, smem_bytes(56, 128)>>>(agg, Wp2, bp2, h2b);
    // layer 3: aggregate h2b (128), GEMM 112 -> 224 + relu -> h3b (bf16, 224)
    k_agg128b<<<ablk, 256>>>(h2b, agg);
    k_gemm_mma<112, 224><<<gblk, 256, smem_bytes(112, 224)>>>(agg, Wp3, bp3, h3b);

    k_pool<<<NG, 224>>>();
    k_mlp1<<<128, 256, mlp1_smem>>>(Wf1, bf1);
    k_mlp2<<<16, 256>>>(Wf2, bf2, out);
}